// round 11
// baseline (speedup 1.0000x reference)
#include <cuda_runtime.h>
#include <cuda_bf16.h>
#include <math.h>

#define HD   20
#define TPB  128
#define CH_W 16
#define XB   96
#define KW   8          // steps per barrier window
#define RING 16         // 2*KW ring slots

typedef unsigned long long ull;

__device__ __forceinline__ float tanh_fast(float x) {
    float y; asm("tanh.approx.f32 %0, %1;" : "=f"(y) : "f"(x)); return y;
}
__device__ __forceinline__ ull pack2(float a, float b) {
    ull r; asm("mov.b64 %0, {%1,%2};" : "=l"(r) : "f"(a), "f"(b)); return r;
}
__device__ __forceinline__ float2 unpack2(ull p) {
    float2 v; asm("mov.b64 {%0,%1}, %2;" : "=f"(v.x), "=f"(v.y) : "l"(p)); return v;
}
__device__ __forceinline__ ull ffma2(ull a, ull b, ull c) {
    ull r; asm("fma.rn.f32x2 %0, %1, %2, %3;" : "=l"(r) : "l"(a), "l"(b), "l"(c)); return r;
}
__device__ __forceinline__ float hsum(ull p) {
    float2 v = unpack2(p); return v.x + v.y;
}

__device__ __forceinline__ void lstm_act4(ull aI, ull aF, ull aG, ull aO,
                                          float& cst, float& h) {
    float pi = hsum(aI), pf = hsum(aF), pg = hsum(aG), po = hsum(aO);
    float gi = fmaf(tanh_fast(0.5f * pi), 0.5f, 0.5f);
    float gf = fmaf(tanh_fast(0.5f * pf), 0.5f, 0.5f);
    float gg = tanh_fast(pg);
    float go = fmaf(tanh_fast(0.5f * po), 0.5f, 0.5f);
    cst = fmaf(gf, cst, gi * gg);
    h   = go * tanh_fast(cst);
}

// 20-dim dot for 4 gates; HB = float4-pair view of 20 floats (+12 zero pad).
#define DOT20(HB, aI, aF, aG, aO) do {                                        \
    _Pragma("unroll")                                                         \
    for (int j = 0; j < 5; j++) {                                             \
        ulonglong2 hp = (HB)[j];                                              \
        aI = ffma2(wI[2*j], hp.x, aI); aI = ffma2(wI[2*j+1], hp.y, aI);       \
        aF = ffma2(wF[2*j], hp.x, aF); aF = ffma2(wF[2*j+1], hp.y, aF);       \
        aG = ffma2(wG[2*j], hp.x, aG); aG = ffma2(wG[2*j+1], hp.y, aG);       \
        aO = ffma2(wO[2*j], hp.x, aO); aO = ffma2(wO[2*j+1], hp.y, aO);       \
    }                                                                         \
} while (0)

// 128 threads/block, one pipeline STAGE per warp, TWO chunks (A,B) per warp:
//   w0 (SMSP0): L1 LSTM  @ window w    -> h0ring[c][t&15]
//   w2 (SMSP2): proj     @ window w-1  -> prring[c][tp&15]
//   w1 (SMSP1): L2 LSTM  @ window w-2  -> h1ring[c][t1&15]
//   w3 (SMSP3): linear head + store @ window w-3
// All 4 SMSPs active; each warp holds ONE weight set shared by both chunks.
__global__ __launch_bounds__(TPB, 4)
void lstm_opt_kernel(const float* __restrict__ grad,
                     const float* __restrict__ Wih0, const float* __restrict__ Whh0,
                     const float* __restrict__ bih0, const float* __restrict__ bhh0,
                     const float* __restrict__ Wih1, const float* __restrict__ Whh1,
                     const float* __restrict__ bih1, const float* __restrict__ bhh1,
                     const float* __restrict__ Wlin, const float* __restrict__ blin,
                     float* __restrict__ out, int N, int out_size, int chl)
{
    __shared__ __align__(16) float2 xbuf[2][XB];
    __shared__ __align__(16) float  h0ring[2][RING][32];
    __shared__ __align__(16) float4 prring[2][RING][32];
    __shared__ __align__(16) float  h1ring[2][RING][32];

    const int tid  = threadIdx.x;
    const int wid  = tid >> 5;
    const int lane = tid & 31;
    const int u    = lane;
    const bool act = (u < HD);

    // ---- per-warp weights: per-gate, k-pair packed (one set per warp) ----
    ull wI[10], wF[10], wG[10], wO[10];
    ull bI = 0ull, bF = 0ull, bG = 0ull, bO = 0ull;
    ull wxI = 0ull, wxF = 0ull, wxG = 0ull, wxO = 0ull;
    float wlin_u = 0.f;
    #pragma unroll
    for (int k = 0; k < 10; k++) { wI[k]=0ull; wF[k]=0ull; wG[k]=0ull; wO[k]=0ull; }

    if (act) {
        const float* W = (wid == 0) ? Whh0 : (wid == 1) ? Whh1 : Wih1;
        if (wid < 3) {
            #pragma unroll
            for (int k = 0; k < 10; k++) {
                wI[k] = pack2(W[u * HD + 2*k],            W[u * HD + 2*k + 1]);
                wF[k] = pack2(W[(HD + u) * HD + 2*k],     W[(HD + u) * HD + 2*k + 1]);
                wG[k] = pack2(W[(2 * HD + u) * HD + 2*k], W[(2 * HD + u) * HD + 2*k + 1]);
                wO[k] = pack2(W[(3 * HD + u) * HD + 2*k], W[(3 * HD + u) * HD + 2*k + 1]);
            }
        }
        if (wid == 0) {           // L1: x-projection weights + L1 biases
            wxI = pack2(Wih0[u * 2 + 0],            Wih0[u * 2 + 1]);
            wxF = pack2(Wih0[(HD + u) * 2 + 0],     Wih0[(HD + u) * 2 + 1]);
            wxG = pack2(Wih0[(2 * HD + u) * 2 + 0], Wih0[(2 * HD + u) * 2 + 1]);
            wxO = pack2(Wih0[(3 * HD + u) * 2 + 0], Wih0[(3 * HD + u) * 2 + 1]);
            bI = pack2(bih0[u] + bhh0[u], 0.f);
            bF = pack2(bih0[HD + u] + bhh0[HD + u], 0.f);
            bG = pack2(bih0[2 * HD + u] + bhh0[2 * HD + u], 0.f);
            bO = pack2(bih0[3 * HD + u] + bhh0[3 * HD + u], 0.f);
        } else if (wid == 2) {    // proj: L2 biases folded here
            bI = pack2(bih1[u] + bhh1[u], 0.f);
            bF = pack2(bih1[HD + u] + bhh1[HD + u], 0.f);
            bG = pack2(bih1[2 * HD + u] + bhh1[2 * HD + u], 0.f);
            bO = pack2(bih1[3 * HD + u] + bhh1[3 * HD + u], 0.f);
        } else if (wid == 3) {
            wlin_u = Wlin[u];
        }
    }
    const float blinsc = blin[0] * 0.01f;

    // ---- two chunks per block ----
    const int startA = blockIdx.x * 2 * chl;
    if (startA >= N) return;
    const int endA  = min(N, startA + chl);
    const int s2A   = max(0, startA - CH_W);
    const int s1A   = max(0, s2A - CH_W);
    const int spanA = endA - s1A;
    const int i2A   = s2A - s1A;
    const int ihlA  = startA - s1A;

    const int startB = startA + chl;
    const bool liveB = (startB < N);
    const int endB   = liveB ? min(N, startB + chl) : 0;
    const int s2B    = liveB ? max(0, startB - CH_W) : 0;
    const int s1B    = liveB ? max(0, s2B - CH_W) : 0;
    const int spanB  = liveB ? (endB - s1B) : -1;
    const int i2B    = liveB ? (s2B - s1B) : (1 << 28);
    const int ihlB   = liveB ? (startB - s1B) : (1 << 28);

    // ---- preprocess grad -> (log, sign) features, both chunks ----
    for (int i = tid; i < XB; i += TPB) {
        float gA  = grad[min(s1A + i, N - 1)];
        float lgA = fminf(1.f, fmaxf(-1.f, __logf(fabsf(gA) + 1e-8f) * 0.1f));
        float sgA = fminf(1.f, fmaxf(-1.f, gA * 22026.4657948067f));   // exp(10)
        xbuf[0][i] = make_float2(lgA, sgA);
        float gB  = grad[min(s1B + i, N - 1)];
        float lgB = fminf(1.f, fmaxf(-1.f, __logf(fabsf(gB) + 1e-8f) * 0.1f));
        float sgB = fminf(1.f, fmaxf(-1.f, gB * 22026.4657948067f));
        xbuf[1][i] = make_float2(lgB, sgB);
    }
    for (int i = tid; i < 2 * RING * 32; i += TPB) {
        ((float*)h0ring)[i] = 0.f;
        ((float*)h1ring)[i] = 0.f;
        ((float4*)prring)[i] = make_float4(0.f, 0.f, 0.f, 0.f);
    }
    __syncthreads();

    float csA = 0.f, hA = 0.f, csB = 0.f, hB = 0.f;

#define L1S(C, T, CS, HS) do {                                                \
    float2 xv = xbuf[C][T];                                                   \
    ull xp = pack2(xv.x, xv.y);                                               \
    ull aI = ffma2(wxI, xp, bI), aF = ffma2(wxF, xp, bF);                     \
    ull aG = ffma2(wxG, xp, bG), aO = ffma2(wxO, xp, bO);                     \
    const ulonglong2* hb =                                                    \
        (const ulonglong2*)h0ring[C][((T) + RING - 1) & (RING - 1)];          \
    DOT20(hb, aI, aF, aG, aO);                                                \
    lstm_act4(aI, aF, aG, aO, CS, HS);                                        \
    h0ring[C][(T) & (RING - 1)][u] = HS;                                      \
} while (0)

#define PROJS(C, T) do {                                                      \
    ull aI = bI, aF = bF, aG = bG, aO = bO;                                   \
    const ulonglong2* yb = (const ulonglong2*)h0ring[C][(T) & (RING - 1)];    \
    DOT20(yb, aI, aF, aG, aO);                                                \
    prring[C][(T) & (RING - 1)][u] =                                          \
        make_float4(hsum(aI), hsum(aF), hsum(aG), hsum(aO));                  \
} while (0)

#define L2S(C, T, CS, HS) do {                                                \
    float4 pv = prring[C][(T) & (RING - 1)][u];                               \
    ull aI = pack2(pv.x, 0.f), aF = pack2(pv.y, 0.f);                         \
    ull aG = pack2(pv.z, 0.f), aO = pack2(pv.w, 0.f);                         \
    const ulonglong2* hb =                                                    \
        (const ulonglong2*)h1ring[C][((T) + RING - 1) & (RING - 1)];          \
    DOT20(hb, aI, aF, aG, aO);                                                \
    lstm_act4(aI, aF, aG, aO, CS, HS);                                        \
    h1ring[C][(T) & (RING - 1)][u] = HS;                                      \
} while (0)

#define HEADS(C, T, S1) do {                                                  \
    float hv = h1ring[C][(T) & (RING - 1)][u];                                \
    float part = hv * wlin_u;                                                 \
    part += __shfl_xor_sync(0xFFFFFFFFu, part, 16);                           \
    part += __shfl_xor_sync(0xFFFFFFFFu, part, 8);                            \
    part += __shfl_xor_sync(0xFFFFFFFFu, part, 4);                            \
    part += __shfl_xor_sync(0xFFFFFFFFu, part, 2);                            \
    part += __shfl_xor_sync(0xFFFFFFFFu, part, 1);                            \
    if (lane == 0) out[(S1) + (T)] = fmaf(part, 0.01f, blinsc);               \
} while (0)

    const int spanMax = max(spanA, spanB);
    const int NW = (spanMax + KW - 1) / KW + 3;

    for (int w = 0; w < NW; ++w) {
        if (wid == 0) {
            #pragma unroll
            for (int k = 0; k < KW; ++k) {
                const int t = w * KW + k;
                if (t < spanA) L1S(0, t, csA, hA);
                if (t < spanB) L1S(1, t, csB, hB);
                __syncwarp();
            }
        } else if (wid == 2) {
            #pragma unroll
            for (int k = 0; k < KW; ++k) {
                const int tp = (w - 1) * KW + k;
                if (tp >= i2A && tp < spanA) PROJS(0, tp);
                if (tp >= i2B && tp < spanB) PROJS(1, tp);
            }
        } else if (wid == 1) {
            #pragma unroll
            for (int k = 0; k < KW; ++k) {
                const int t1 = (w - 2) * KW + k;
                if (t1 >= i2A && t1 < spanA) L2S(0, t1, csA, hA);
                if (t1 >= i2B && t1 < spanB) L2S(1, t1, csB, hB);
                __syncwarp();
            }
        } else {
            #pragma unroll
            for (int k = 0; k < KW; ++k) {
                const int th = (w - 3) * KW + k;
                if (th >= ihlA && th < spanA) HEADS(0, th, s1A);
                if (th >= ihlB && th < spanB) HEADS(1, th, s1B);
            }
        }
        __syncthreads();
    }

    // final states: [update(N), h0(20), h1(20), c0(20), c1(20)]
    if (out_size >= N + 80 && act) {
        if (wid == 0) {
            if (endA == N)          { out[N + u]      = hA; out[N + 40 + u] = csA; }
            if (liveB && endB == N) { out[N + u]      = hB; out[N + 40 + u] = csB; }
        } else if (wid == 1) {
            if (endA == N)          { out[N + 20 + u] = hA; out[N + 60 + u] = csA; }
            if (liveB && endB == N) { out[N + 20 + u] = hB; out[N + 60 + u] = csB; }
        }
    }
}

extern "C" void kernel_launch(void* const* d_in, const int* in_sizes, int n_in,
                              void* d_out, int out_size) {
    const float* grad = (const float*)d_in[0];
    const float* Wih0 = (const float*)d_in[1];
    const float* Whh0 = (const float*)d_in[2];
    const float* bih0 = (const float*)d_in[3];
    const float* bhh0 = (const float*)d_in[4];
    const float* Wih1 = (const float*)d_in[5];
    const float* Whh1 = (const float*)d_in[6];
    const float* bih1 = (const float*)d_in[7];
    const float* bhh1 = (const float*)d_in[8];
    const float* Wlin = (const float*)d_in[9];
    const float* blin = (const float*)d_in[10];

    int N = in_sizes[0];
    // 1184 chunk slots = 4 blocks/SM x 148 SMs x 2 chunks/block, one wave
    int chl = (N + 1183) / 1184;
    if (chl > XB - 2 * CH_W) chl = XB - 2 * CH_W;
    if (chl < 1) chl = 1;
    int grid = (N + 2 * chl - 1) / (2 * chl);
    lstm_opt_kernel<<<grid, TPB>>>(grad, Wih0, Whh0, bih0, bhh0,
                                   Wih1, Whh1, bih1, bhh1, Wlin, blin,
                                   (float*)d_out, N, out_size, chl);
}

// round 12
// speedup vs baseline: 1.5748x; 1.5748x over previous
#include <cuda_runtime.h>
#include <cuda_bf16.h>
#include <math.h>

#define HD   20
#define TPB  128
#define CH_W 12
#define XB   144
#define KW   8          // steps per barrier window
#define RING 16         // 2*KW ring slots

typedef unsigned long long ull;

__device__ __forceinline__ float tanh_fast(float x) {
    float y; asm("tanh.approx.f32 %0, %1;" : "=f"(y) : "f"(x)); return y;
}
__device__ __forceinline__ ull pack2(float a, float b) {
    ull r; asm("mov.b64 %0, {%1,%2};" : "=l"(r) : "f"(a), "f"(b)); return r;
}
__device__ __forceinline__ float2 unpack2(ull p) {
    float2 v; asm("mov.b64 {%0,%1}, %2;" : "=f"(v.x), "=f"(v.y) : "l"(p)); return v;
}
__device__ __forceinline__ ull ffma2(ull a, ull b, ull c) {
    ull r; asm("fma.rn.f32x2 %0, %1, %2, %3;" : "=l"(r) : "l"(a), "l"(b), "l"(c)); return r;
}
__device__ __forceinline__ float hsum(ull p) {
    float2 v = unpack2(p); return v.x + v.y;
}

__device__ __forceinline__ void lstm_act4(ull aI, ull aF, ull aG, ull aO,
                                          float& cst, float& h) {
    float pi = hsum(aI), pf = hsum(aF), pg = hsum(aG), po = hsum(aO);
    float gi = fmaf(tanh_fast(0.5f * pi), 0.5f, 0.5f);
    float gf = fmaf(tanh_fast(0.5f * pf), 0.5f, 0.5f);
    float gg = tanh_fast(pg);
    float go = fmaf(tanh_fast(0.5f * po), 0.5f, 0.5f);
    cst = fmaf(gf, cst, gi * gg);
    h   = go * tanh_fast(cst);
}

// 20-dim dot for 4 gates; HB = float4-pair view of 20 floats (+12 zero pad).
#define DOT20(HB, aI, aF, aG, aO) do {                                        \
    _Pragma("unroll")                                                         \
    for (int j = 0; j < 5; j++) {                                             \
        ulonglong2 hp = (HB)[j];                                              \
        aI = ffma2(wI[2*j], hp.x, aI); aI = ffma2(wI[2*j+1], hp.y, aI);       \
        aF = ffma2(wF[2*j], hp.x, aF); aF = ffma2(wF[2*j+1], hp.y, aF);       \
        aG = ffma2(wG[2*j], hp.x, aG); aG = ffma2(wG[2*j+1], hp.y, aG);       \
        aO = ffma2(wO[2*j], hp.x, aO); aO = ffma2(wO[2*j+1], hp.y, aO);       \
    }                                                                         \
} while (0)

// 128 threads/block, ONE chunk per block, 4-warp window pipeline (KW=8):
//   w0 (SMSP0): L1 LSTM  time-window w   -> h0ring[t&15]   (plain float)
//   w2 (SMSP2): proj     time-window w-1 -> prring[tp&15]  (float4 pre-acts)
//   w1 (SMSP1): L2 LSTM  time-window w-2 -> h1ring[t1&15]
//   w3 (SMSP3): linear head + store, time-window w-3 (reads h1ring)
// Lane u owns unit u. One 80-reg weight set per warp; head warp is light.
__global__ __launch_bounds__(TPB, 4)
void lstm_opt_kernel(const float* __restrict__ grad,
                     const float* __restrict__ Wih0, const float* __restrict__ Whh0,
                     const float* __restrict__ bih0, const float* __restrict__ bhh0,
                     const float* __restrict__ Wih1, const float* __restrict__ Whh1,
                     const float* __restrict__ bih1, const float* __restrict__ bhh1,
                     const float* __restrict__ Wlin, const float* __restrict__ blin,
                     float* __restrict__ out, int N, int out_size, int chl)
{
    __shared__ __align__(16) float2 xbuf[XB];
    __shared__ __align__(16) float  h0ring[RING][32];
    __shared__ __align__(16) float4 prring[RING][32];
    __shared__ __align__(16) float  h1ring[RING][32];

    const int tid  = threadIdx.x;
    const int wid  = tid >> 5;
    const int lane = tid & 31;
    const int u    = lane;
    const bool act = (u < HD);

    // ---- per-warp weights: per-gate, k-pair packed ----
    ull wI[10], wF[10], wG[10], wO[10];
    ull bI = 0ull, bF = 0ull, bG = 0ull, bO = 0ull;
    ull wxI = 0ull, wxF = 0ull, wxG = 0ull, wxO = 0ull;
    float wlin_u = 0.f;
    #pragma unroll
    for (int k = 0; k < 10; k++) { wI[k]=0ull; wF[k]=0ull; wG[k]=0ull; wO[k]=0ull; }

    if (act) {
        if (wid < 3) {
            const float* W = (wid == 0) ? Whh0 : (wid == 1) ? Whh1 : Wih1;
            #pragma unroll
            for (int k = 0; k < 10; k++) {
                wI[k] = pack2(W[u * HD + 2*k],            W[u * HD + 2*k + 1]);
                wF[k] = pack2(W[(HD + u) * HD + 2*k],     W[(HD + u) * HD + 2*k + 1]);
                wG[k] = pack2(W[(2 * HD + u) * HD + 2*k], W[(2 * HD + u) * HD + 2*k + 1]);
                wO[k] = pack2(W[(3 * HD + u) * HD + 2*k], W[(3 * HD + u) * HD + 2*k + 1]);
            }
        }
        if (wid == 0) {           // L1: x-projection weights + L1 biases
            wxI = pack2(Wih0[u * 2 + 0],            Wih0[u * 2 + 1]);
            wxF = pack2(Wih0[(HD + u) * 2 + 0],     Wih0[(HD + u) * 2 + 1]);
            wxG = pack2(Wih0[(2 * HD + u) * 2 + 0], Wih0[(2 * HD + u) * 2 + 1]);
            wxO = pack2(Wih0[(3 * HD + u) * 2 + 0], Wih0[(3 * HD + u) * 2 + 1]);
            bI = pack2(bih0[u] + bhh0[u], 0.f);
            bF = pack2(bih0[HD + u] + bhh0[HD + u], 0.f);
            bG = pack2(bih0[2 * HD + u] + bhh0[2 * HD + u], 0.f);
            bO = pack2(bih0[3 * HD + u] + bhh0[3 * HD + u], 0.f);
        } else if (wid == 2) {    // proj: L2 biases folded here
            bI = pack2(bih1[u] + bhh1[u], 0.f);
            bF = pack2(bih1[HD + u] + bhh1[HD + u], 0.f);
            bG = pack2(bih1[2 * HD + u] + bhh1[2 * HD + u], 0.f);
            bO = pack2(bih1[3 * HD + u] + bhh1[3 * HD + u], 0.f);
        } else if (wid == 3) {    // head
            wlin_u = Wlin[u];
        }
    }
    const float blinsc = blin[0] * 0.01f;

    // ---- chunk ranges ----
    const int start_out = blockIdx.x * chl;
    if (start_out >= N) return;
    const int end_out = min(N, start_out + chl);
    const int s2      = max(0, start_out - CH_W);
    const int s1      = max(0, s2 - CH_W);
    const int span    = end_out - s1;
    const int i2      = s2 - s1;           // first L2-active step
    const int ihl     = start_out - s1;    // first head-output step

    // ---- preprocess + zero-init ----
    for (int i = tid; i < span; i += TPB) {
        float g  = grad[s1 + i];
        float lg = fminf(1.f, fmaxf(-1.f, __logf(fabsf(g) + 1e-8f) * 0.1f));
        float sg = fminf(1.f, fmaxf(-1.f, g * 22026.4657948067f));   // exp(10)
        xbuf[i] = make_float2(lg, sg);
    }
    for (int i = tid; i < RING * 32; i += TPB) {
        ((float*)h0ring)[i] = 0.f;
        ((float*)h1ring)[i] = 0.f;
        ((float4*)prring)[i] = make_float4(0.f, 0.f, 0.f, 0.f);
    }
    __syncthreads();

    float cst = 0.f, h = 0.f;
    const int NW = (span + KW - 1) / KW + 3;

    for (int w = 0; w < NW; ++w) {
        if (wid == 0) {
            // ---- L1: time steps [w*KW, w*KW+KW) ----
            #pragma unroll
            for (int k = 0; k < KW; ++k) {
                const int t = w * KW + k;
                if (t < span) {
                    float2 xv = xbuf[t];
                    ull xp = pack2(xv.x, xv.y);
                    ull aI = ffma2(wxI, xp, bI);
                    ull aF = ffma2(wxF, xp, bF);
                    ull aG = ffma2(wxG, xp, bG);
                    ull aO = ffma2(wxO, xp, bO);
                    const ulonglong2* hb =
                        (const ulonglong2*)h0ring[(t + RING - 1) & (RING - 1)];
                    DOT20(hb, aI, aF, aG, aO);
                    lstm_act4(aI, aF, aG, aO, cst, h);
                    h0ring[t & (RING - 1)][u] = h;
                }
                __syncwarp();
            }
        } else if (wid == 2) {
            // ---- proj: time steps [(w-1)*KW, ...) ----
            #pragma unroll
            for (int k = 0; k < KW; ++k) {
                const int tp = (w - 1) * KW + k;
                if (tp >= i2 && tp < span) {
                    ull aI = bI, aF = bF, aG = bG, aO = bO;
                    const ulonglong2* yb =
                        (const ulonglong2*)h0ring[tp & (RING - 1)];
                    DOT20(yb, aI, aF, aG, aO);
                    prring[tp & (RING - 1)][u] =
                        make_float4(hsum(aI), hsum(aF), hsum(aG), hsum(aO));
                }
            }
        } else if (wid == 1) {
            // ---- L2: time steps [(w-2)*KW, ...) ----
            #pragma unroll
            for (int k = 0; k < KW; ++k) {
                const int t1 = (w - 2) * KW + k;
                if (t1 >= i2 && t1 < span) {
                    float4 pv = prring[t1 & (RING - 1)][u];
                    ull aI = pack2(pv.x, 0.f), aF = pack2(pv.y, 0.f);
                    ull aG = pack2(pv.z, 0.f), aO = pack2(pv.w, 0.f);
                    const ulonglong2* hb =
                        (const ulonglong2*)h1ring[(t1 + RING - 1) & (RING - 1)];
                    DOT20(hb, aI, aF, aG, aO);
                    lstm_act4(aI, aF, aG, aO, cst, h);
                    h1ring[t1 & (RING - 1)][u] = h;
                }
                __syncwarp();
            }
        } else {
            // ---- head: time steps [(w-3)*KW, ...) (h1ring written last window) ----
            #pragma unroll
            for (int k = 0; k < KW; ++k) {
                const int th = (w - 3) * KW + k;
                if (th >= ihl && th < span) {
                    float hv = h1ring[th & (RING - 1)][u];
                    float part = hv * wlin_u;            // zero on idle lanes
                    part += __shfl_xor_sync(0xFFFFFFFFu, part, 16);
                    part += __shfl_xor_sync(0xFFFFFFFFu, part, 8);
                    part += __shfl_xor_sync(0xFFFFFFFFu, part, 4);
                    part += __shfl_xor_sync(0xFFFFFFFFu, part, 2);
                    part += __shfl_xor_sync(0xFFFFFFFFu, part, 1);
                    if (lane == 0) out[s1 + th] = fmaf(part, 0.01f, blinsc);
                }
            }
        }
        __syncthreads();
    }

    // final states: [update(N), h0(20), h1(20), c0(20), c1(20)]
    if (end_out == N && out_size >= N + 80 && act) {
        if (wid == 0)      { out[N + u]      = h; out[N + 40 + u] = cst; }
        else if (wid == 1) { out[N + 20 + u] = h; out[N + 60 + u] = cst; }
    }
}

extern "C" void kernel_launch(void* const* d_in, const int* in_sizes, int n_in,
                              void* d_out, int out_size) {
    const float* grad = (const float*)d_in[0];
    const float* Wih0 = (const float*)d_in[1];
    const float* Whh0 = (const float*)d_in[2];
    const float* bih0 = (const float*)d_in[3];
    const float* bhh0 = (const float*)d_in[4];
    const float* Wih1 = (const float*)d_in[5];
    const float* Whh1 = (const float*)d_in[6];
    const float* bih1 = (const float*)d_in[7];
    const float* bhh1 = (const float*)d_in[8];
    const float* Wlin = (const float*)d_in[9];
    const float* blin = (const float*)d_in[10];

    int N = in_sizes[0];
    // 592 chunk slots = 4 blocks/SM x 148 SMs, one wave
    int chl = (N + 591) / 592;
    if (chl > XB - 2 * CH_W - 1) chl = XB - 2 * CH_W - 1;
    if (chl < 1) chl = 1;
    int grid = (N + chl - 1) / chl;
    lstm_opt_kernel<<<grid, TPB>>>(grad, Wih0, Whh0, bih0, bhh0,
                                   Wih1, Whh1, bih1, bhh1, Wlin, blin,
                                   (float*)d_out, N, out_size, chl);
}

// round 13
// speedup vs baseline: 1.6101x; 1.0224x over previous
#include <cuda_runtime.h>
#include <cuda_bf16.h>
#include <math.h>

#define HD   20
#define TPB  128
#define CH_W 12
#define XB   144
#define KW   4          // steps per barrier window
#define RING 8          // 2*KW ring slots

typedef unsigned long long ull;

__device__ __forceinline__ float tanh_fast(float x) {
    float y; asm("tanh.approx.f32 %0, %1;" : "=f"(y) : "f"(x)); return y;
}
__device__ __forceinline__ ull pack2(float a, float b) {
    ull r; asm("mov.b64 %0, {%1,%2};" : "=l"(r) : "f"(a), "f"(b)); return r;
}
__device__ __forceinline__ float2 unpack2(ull p) {
    float2 v; asm("mov.b64 {%0,%1}, %2;" : "=f"(v.x), "=f"(v.y) : "l"(p)); return v;
}
__device__ __forceinline__ ull ffma2(ull a, ull b, ull c) {
    ull r; asm("fma.rn.f32x2 %0, %1, %2, %3;" : "=l"(r) : "l"(a), "l"(b), "l"(c)); return r;
}
__device__ __forceinline__ float hsum(ull p) {
    float2 v = unpack2(p); return v.x + v.y;
}

__device__ __forceinline__ void lstm_act4(ull aI, ull aF, ull aG, ull aO,
                                          float& cst, float& h) {
    float pi = hsum(aI), pf = hsum(aF), pg = hsum(aG), po = hsum(aO);
    float gi = fmaf(tanh_fast(0.5f * pi), 0.5f, 0.5f);
    float gf = fmaf(tanh_fast(0.5f * pf), 0.5f, 0.5f);
    float gg = tanh_fast(pg);
    float go = fmaf(tanh_fast(0.5f * po), 0.5f, 0.5f);
    cst = fmaf(gf, cst, gi * gg);
    h   = go * tanh_fast(cst);
}

// 20-dim dot for 4 gates; HB = float4-pair view of 20 floats (+12 zero pad).
#define DOT20(HB, aI, aF, aG, aO) do {                                        \
    _Pragma("unroll")                                                         \
    for (int j = 0; j < 5; j++) {                                             \
        ulonglong2 hp = (HB)[j];                                              \
        aI = ffma2(wI[2*j], hp.x, aI); aI = ffma2(wI[2*j+1], hp.y, aI);       \
        aF = ffma2(wF[2*j], hp.x, aF); aF = ffma2(wF[2*j+1], hp.y, aF);       \
        aG = ffma2(wG[2*j], hp.x, aG); aG = ffma2(wG[2*j+1], hp.y, aG);       \
        aO = ffma2(wO[2*j], hp.x, aO); aO = ffma2(wO[2*j+1], hp.y, aO);       \
    }                                                                         \
} while (0)

// Stage bodies (T = absolute step index within [0, span))
#define L1BODY(T) do {                                                        \
    float2 xv = xbuf[T];                                                      \
    ull xp = pack2(xv.x, xv.y);                                               \
    ull aI = ffma2(wxI, xp, bI);                                              \
    ull aF = ffma2(wxF, xp, bF);                                              \
    ull aG = ffma2(wxG, xp, bG);                                              \
    ull aO = ffma2(wxO, xp, bO);                                              \
    const ulonglong2* hb =                                                    \
        (const ulonglong2*)h0ring[((T) + RING - 1) & (RING - 1)];             \
    DOT20(hb, aI, aF, aG, aO);                                                \
    lstm_act4(aI, aF, aG, aO, cst, h);                                        \
    h0ring[(T) & (RING - 1)][u] = h;                                          \
} while (0)

#define PROJBODY(T) do {                                                      \
    ull aI = bI, aF = bF, aG = bG, aO = bO;                                   \
    const ulonglong2* yb = (const ulonglong2*)h0ring[(T) & (RING - 1)];       \
    DOT20(yb, aI, aF, aG, aO);                                                \
    prring[(T) & (RING - 1)][u] =                                             \
        make_float4(hsum(aI), hsum(aF), hsum(aG), hsum(aO));                  \
} while (0)

#define L2BODY(T) do {                                                        \
    float4 pv = prring[(T) & (RING - 1)][u];                                  \
    ull aI = pack2(pv.x, 0.f), aF = pack2(pv.y, 0.f);                         \
    ull aG = pack2(pv.z, 0.f), aO = pack2(pv.w, 0.f);                         \
    const ulonglong2* hb =                                                    \
        (const ulonglong2*)h1ring[((T) + RING - 1) & (RING - 1)];             \
    DOT20(hb, aI, aF, aG, aO);                                                \
    lstm_act4(aI, aF, aG, aO, cst, h);                                        \
    h1ring[(T) & (RING - 1)][u] = h;                                          \
} while (0)

#define HEADBODY(T) do {                                                      \
    float hv = h1ring[(T) & (RING - 1)][u];                                   \
    float part = hv * wlin_u;                                                 \
    part += __shfl_xor_sync(0xFFFFFFFFu, part, 16);                           \
    part += __shfl_xor_sync(0xFFFFFFFFu, part, 8);                            \
    part += __shfl_xor_sync(0xFFFFFFFFu, part, 4);                            \
    part += __shfl_xor_sync(0xFFFFFFFFu, part, 2);                            \
    part += __shfl_xor_sync(0xFFFFFFFFu, part, 1);                            \
    if (lane == 0) out[s1 + (T)] = fmaf(part, 0.01f, blinsc);                 \
} while (0)

// 128 threads/block, ONE chunk per block, 4-warp window pipeline (KW=4),
// per-stage PEELED windows (clean fast path, guarded edge path):
//   w0 (SMSP0): L1 LSTM  window w    -> h0ring[t&7]
//   w2 (SMSP2): proj     window w-1  -> prring[tp&7]
//   w1 (SMSP1): L2 LSTM  window w-2  -> h1ring[t1&7]
//   w3 (SMSP3): linear head + store, window w-3
__global__ __launch_bounds__(TPB, 4)
void lstm_opt_kernel(const float* __restrict__ grad,
                     const float* __restrict__ Wih0, const float* __restrict__ Whh0,
                     const float* __restrict__ bih0, const float* __restrict__ bhh0,
                     const float* __restrict__ Wih1, const float* __restrict__ Whh1,
                     const float* __restrict__ bih1, const float* __restrict__ bhh1,
                     const float* __restrict__ Wlin, const float* __restrict__ blin,
                     float* __restrict__ out, int N, int out_size, int chl)
{
    __shared__ __align__(16) float2 xbuf[XB];
    __shared__ __align__(16) float  h0ring[RING][32];
    __shared__ __align__(16) float4 prring[RING][32];
    __shared__ __align__(16) float  h1ring[RING][32];

    const int tid  = threadIdx.x;
    const int wid  = tid >> 5;
    const int lane = tid & 31;
    const int u    = lane;
    const bool act = (u < HD);

    // ---- per-warp weights: per-gate, k-pair packed ----
    ull wI[10], wF[10], wG[10], wO[10];
    ull bI = 0ull, bF = 0ull, bG = 0ull, bO = 0ull;
    ull wxI = 0ull, wxF = 0ull, wxG = 0ull, wxO = 0ull;
    float wlin_u = 0.f;
    #pragma unroll
    for (int k = 0; k < 10; k++) { wI[k]=0ull; wF[k]=0ull; wG[k]=0ull; wO[k]=0ull; }

    if (act) {
        if (wid < 3) {
            const float* W = (wid == 0) ? Whh0 : (wid == 1) ? Whh1 : Wih1;
            #pragma unroll
            for (int k = 0; k < 10; k++) {
                wI[k] = pack2(W[u * HD + 2*k],            W[u * HD + 2*k + 1]);
                wF[k] = pack2(W[(HD + u) * HD + 2*k],     W[(HD + u) * HD + 2*k + 1]);
                wG[k] = pack2(W[(2 * HD + u) * HD + 2*k], W[(2 * HD + u) * HD + 2*k + 1]);
                wO[k] = pack2(W[(3 * HD + u) * HD + 2*k], W[(3 * HD + u) * HD + 2*k + 1]);
            }
        }
        if (wid == 0) {           // L1: x-projection weights + L1 biases
            wxI = pack2(Wih0[u * 2 + 0],            Wih0[u * 2 + 1]);
            wxF = pack2(Wih0[(HD + u) * 2 + 0],     Wih0[(HD + u) * 2 + 1]);
            wxG = pack2(Wih0[(2 * HD + u) * 2 + 0], Wih0[(2 * HD + u) * 2 + 1]);
            wxO = pack2(Wih0[(3 * HD + u) * 2 + 0], Wih0[(3 * HD + u) * 2 + 1]);
            bI = pack2(bih0[u] + bhh0[u], 0.f);
            bF = pack2(bih0[HD + u] + bhh0[HD + u], 0.f);
            bG = pack2(bih0[2 * HD + u] + bhh0[2 * HD + u], 0.f);
            bO = pack2(bih0[3 * HD + u] + bhh0[3 * HD + u], 0.f);
        } else if (wid == 2) {    // proj: L2 biases folded here
            bI = pack2(bih1[u] + bhh1[u], 0.f);
            bF = pack2(bih1[HD + u] + bhh1[HD + u], 0.f);
            bG = pack2(bih1[2 * HD + u] + bhh1[2 * HD + u], 0.f);
            bO = pack2(bih1[3 * HD + u] + bhh1[3 * HD + u], 0.f);
        } else if (wid == 3) {    // head
            wlin_u = Wlin[u];
        }
    }
    const float blinsc = blin[0] * 0.01f;

    // ---- chunk ranges ----
    const int start_out = blockIdx.x * chl;
    if (start_out >= N) return;
    const int end_out = min(N, start_out + chl);
    const int s2      = max(0, start_out - CH_W);
    const int s1      = max(0, s2 - CH_W);
    const int span    = end_out - s1;
    const int i2      = s2 - s1;           // first L2-active step
    const int ihl     = start_out - s1;    // first head-output step

    // ---- preprocess + zero-init ----
    for (int i = tid; i < span; i += TPB) {
        float g  = grad[s1 + i];
        float lg = fminf(1.f, fmaxf(-1.f, __logf(fabsf(g) + 1e-8f) * 0.1f));
        float sg = fminf(1.f, fmaxf(-1.f, g * 22026.4657948067f));   // exp(10)
        xbuf[i] = make_float2(lg, sg);
    }
    for (int i = tid; i < RING * 32; i += TPB) {
        ((float*)h0ring)[i] = 0.f;
        ((float*)h1ring)[i] = 0.f;
        ((float4*)prring)[i] = make_float4(0.f, 0.f, 0.f, 0.f);
    }
    __syncthreads();

    float cst = 0.f, h = 0.f;
    const int NW = (span + KW - 1) / KW + 3;

    for (int w = 0; w < NW; ++w) {
        if (wid == 0) {
            const int t0 = w * KW;
            if (t0 + KW <= span) {                  // clean window
                #pragma unroll
                for (int k = 0; k < KW; ++k) { L1BODY(t0 + k); __syncwarp(); }
            } else {                                // edge window
                #pragma unroll
                for (int k = 0; k < KW; ++k) {
                    if (t0 + k < span) L1BODY(t0 + k);
                    __syncwarp();
                }
            }
        } else if (wid == 2) {
            const int t0 = (w - 1) * KW;
            if (t0 >= i2 && t0 + KW <= span) {
                #pragma unroll
                for (int k = 0; k < KW; ++k) PROJBODY(t0 + k);
            } else {
                #pragma unroll
                for (int k = 0; k < KW; ++k) {
                    const int tp = t0 + k;
                    if (tp >= i2 && tp < span) PROJBODY(tp);
                }
            }
        } else if (wid == 1) {
            const int t0 = (w - 2) * KW;
            if (t0 >= i2 && t0 + KW <= span) {
                #pragma unroll
                for (int k = 0; k < KW; ++k) { L2BODY(t0 + k); __syncwarp(); }
            } else {
                #pragma unroll
                for (int k = 0; k < KW; ++k) {
                    const int t1 = t0 + k;
                    if (t1 >= i2 && t1 < span) L2BODY(t1);
                    __syncwarp();
                }
            }
        } else {
            const int t0 = (w - 3) * KW;
            if (t0 >= ihl && t0 + KW <= span) {
                #pragma unroll
                for (int k = 0; k < KW; ++k) HEADBODY(t0 + k);
            } else {
                #pragma unroll
                for (int k = 0; k < KW; ++k) {
                    const int th = t0 + k;
                    if (th >= ihl && th < span) HEADBODY(th);
                }
            }
        }
        __syncthreads();
    }

    // final states: [update(N), h0(20), h1(20), c0(20), c1(20)]
    if (end_out == N && out_size >= N + 80 && act) {
        if (wid == 0)      { out[N + u]      = h; out[N + 40 + u] = cst; }
        else if (wid == 1) { out[N + 20 + u] = h; out[N + 60 + u] = cst; }
    }
}

extern "C" void kernel_launch(void* const* d_in, const int* in_sizes, int n_in,
                              void* d_out, int out_size) {
    const float* grad = (const float*)d_in[0];
    const float* Wih0 = (const float*)d_in[1];
    const float* Whh0 = (const float*)d_in[2];
    const float* bih0 = (const float*)d_in[3];
    const float* bhh0 = (const float*)d_in[4];
    const float* Wih1 = (const float*)d_in[5];
    const float* Whh1 = (const float*)d_in[6];
    const float* bih1 = (const float*)d_in[7];
    const float* bhh1 = (const float*)d_in[8];
    const float* Wlin = (const float*)d_in[9];
    const float* blin = (const float*)d_in[10];

    int N = in_sizes[0];
    // 592 chunk slots = 4 blocks/SM x 148 SMs, one wave
    int chl = (N + 591) / 592;
    if (chl > XB - 2 * CH_W - 1) chl = XB - 2 * CH_W - 1;
    if (chl < 1) chl = 1;
    int grid = (N + chl - 1) / chl;
    lstm_opt_kernel<<<grid, TPB>>>(grad, Wih0, Whh0, bih0, bhh0,
                                   Wih1, Whh1, bih1, bhh1, Wlin, blin,
                                   (float*)d_out, N, out_size, chl);
}